// round 16
// baseline (speedup 1.0000x reference)
#include <cuda_runtime.h>
#include <cuda_bf16.h>
#include <stdint.h>
#include <math.h>

#define TOTALP  200000
#define Nn      50000
#define CF      32
#define GRES    32
#define PRES    128
#define HID     256
#define NBLK    5

#define MT      64                   // points per CTA
#define THREADS 256                  // 8 warps: 2 warpM x 4 warpN (warp tile 32x64)
#define NBLOCKS (TOTALP / MT)        // 3125 exact

#define SFW     132                  // feature smem row stride (floats)
#define SNW     260                  // net smem row stride (floats)

#define NST     4                    // cp.async pipeline stages
#define KCH     16384                // bytes per ktile chunk (16 k x 256 n x 4B)

// tf32 weight blob per-block layout (bytes): ktile-contiguous fragment-packed b32
#define L0OFF 0                      // Wc  (8 ktiles)
#define L1OFF 131072                 // W0  (16 ktiles)
#define L2OFF 393216                 // W1  (16 ktiles)
#define BLK_STRIDE 655360

__device__ __align__(16) unsigned char g_wblob[(size_t)NBLK * BLK_STRIDE];
__device__ float g_cum[(NBLK + 1) * HID];

// ---------------- low-level helpers ----------------
__device__ __forceinline__ uint32_t s2u(const void* p) {
    uint32_t a;
    asm("{ .reg .u64 t; cvta.to.shared.u64 t, %1; cvt.u32.u64 %0, t; }" : "=r"(a) : "l"(p));
    return a;
}
__device__ __forceinline__ uint32_t lds32(uint32_t a) {
    uint32_t v;
    asm volatile("ld.shared.b32 %0, [%1];" : "=r"(v) : "r"(a));
    return v;
}
__device__ __forceinline__ void sts64(uint32_t a, uint32_t v0, uint32_t v1) {
    asm volatile("st.shared.v2.b32 [%0], {%1, %2};" :: "r"(a), "r"(v0), "r"(v1) : "memory");
}
__device__ __forceinline__ void sts32(uint32_t a, uint32_t v) {
    asm volatile("st.shared.b32 [%0], %1;" :: "r"(a), "r"(v) : "memory");
}
__device__ __forceinline__ uint32_t f2tf32(float f) {
    uint32_t r;
    asm("cvt.rna.tf32.f32 %0, %1;" : "=r"(r) : "f"(f));
    return r;
}
__device__ __forceinline__ void mma_tf32(float* d, uint32_t a0, uint32_t a1,
                                         uint32_t a2, uint32_t a3,
                                         uint32_t b0, uint32_t b1) {
    asm volatile(
        "mma.sync.aligned.m16n8k8.row.col.f32.tf32.tf32.f32 "
        "{%0,%1,%2,%3}, {%4,%5,%6,%7}, {%8,%9}, {%0,%1,%2,%3};"
        : "+f"(d[0]), "+f"(d[1]), "+f"(d[2]), "+f"(d[3])
        : "r"(a0), "r"(a1), "r"(a2), "r"(a3), "r"(b0), "r"(b1));
}
__device__ __forceinline__ void cp16(uint32_t sa, const void* ga) {
    asm volatile("cp.async.cg.shared.global [%0], [%1], 16;" :: "r"(sa), "l"(ga) : "memory");
}
__device__ __forceinline__ void cp_commit() {
    asm volatile("cp.async.commit_group;" ::: "memory");
}
#define CP_WAIT(n) asm volatile("cp.async.wait_group %0;" :: "n"(n) : "memory")

// ---------------- prep kernel: tf32-convert + fragment-pack weights ----------------
// Blob: ktile-major (16KB per ktile), within ktile: ((j*32)+lane)*16 + comp*4,
//  j = n>>3, lane = ((n&7)<<2)|(kr&3), comp = kr>>2.
__global__ void prep_kernel(const float* __restrict__ Wc, const float* __restrict__ W0,
                            const float* __restrict__ W1, const float* __restrict__ bp,
                            const float* __restrict__ bc, const float* __restrict__ b1) {
    const int total = NBLK * 640 * 256;
    for (int i = blockIdx.x * blockDim.x + threadIdx.x; i < total; i += gridDim.x * blockDim.x) {
        int blk = i / (640 * 256);
        int r   = i % (640 * 256);
        int k   = r / 256;
        int n   = r % 256;
        float w; size_t base; int kl;
        if (k < 128)      { kl = k;       w = Wc[((size_t)blk * 128 + kl) * 256 + n]; base = (size_t)blk * BLK_STRIDE + L0OFF; }
        else if (k < 384) { kl = k - 128; w = W0[((size_t)blk * 256 + kl) * 256 + n]; base = (size_t)blk * BLK_STRIDE + L1OFF; }
        else              { kl = k - 384; w = W1[((size_t)blk * 256 + kl) * 256 + n]; base = (size_t)blk * BLK_STRIDE + L2OFF; }
        int t = kl >> 4, kr = kl & 15;
        int j = n >> 3;
        int lane = ((n & 7) << 2) | (kr & 3);
        int comp = kr >> 2;
        size_t off = base + (size_t)t * KCH + (size_t)((j * 32 + lane) * 16 + comp * 4);
        uint32_t tf;
        asm("cvt.rna.tf32.f32 %0, %1;" : "=r"(tf) : "f"(w));
        *(uint32_t*)(g_wblob + off) = tf;
    }
    if (blockIdx.x == 0 && threadIdx.x < 256) {
        int c = threadIdx.x;
        float pre = bp[c];
        for (int i = 0; i < NBLK; i++) {
            g_cum[i * 256 + c] = pre + bc[i * 256 + c];
            pre += bc[i * 256 + c] + b1[i * 256 + c];
        }
        g_cum[NBLK * 256 + c] = pre;
    }
}

// ---------------- shared memory ----------------
struct SMX {
    __align__(1024) unsigned char Bst[NST * KCH];   // 64 KB B pipeline
    float feat[MT * SFW];       // 33792 B
    float na[MT * SNW];         // 66560 B
    float px[MT], py[MT], pz[MT];
    int   bq[MT];
    int   gx0[MT], gy0[MT], gz0[MT];
    float gwx[MT], gwy[MT], gwz[MT];
    int   qx0[MT], qy0[MT], qz0[MT];
    float qwx[MT], qwy[MT], qwz[MT];
    float outp[MT][4];
};

__device__ __forceinline__ float bilin(const float* __restrict__ base,
                                       int ix, int iy, float wu, float wv) {
    int o = (iy << 7) + ix;
    float a = base[o], b = base[o + 1];
    float c = base[o + 128], d = base[o + 129];
    float t0 = a + (b - a) * wu;
    float t1 = c + (d - c) * wu;
    return t0 + (t1 - t0) * wv;
}

// single-pass tf32 GEMM with 4-stage cp.async B pipeline.
template <int KT>
__device__ __forceinline__ void gemm_cp(float acc[2][8][4],
                                        uint32_t aS, int strideE,
                                        const unsigned char* __restrict__ gB,
                                        uint32_t bsS,
                                        int wM, int wN, int lane, int tid) {
    const int r = lane >> 2, c = lane & 3;
    const uint32_t aR0 = aS + (uint32_t)((wM * 32 + r) * strideE + c) * 4u;
    const uint32_t bfrag = (uint32_t)((wN * 8) * 32 + lane) * 16u;

    // prologue: prime NST-1 stages
#pragma unroll
    for (int s = 0; s < NST - 1; s++) {
        uint32_t sa = bsS + s * KCH + tid * 16;
        const unsigned char* ga = gB + (size_t)s * KCH + tid * 16;
#pragma unroll
        for (int i = 0; i < 4; i++) cp16(sa + i * 4096, ga + i * 4096);
        cp_commit();
    }

#pragma unroll
    for (int t = 0; t < KT; t++) {
        CP_WAIT(NST - 2);
        __syncthreads();
        // issue stage t+NST-1 (overwrites stage consumed at iter t-1; barrier above covers it)
        if (t + NST - 1 < KT) {
            int st = (t + NST - 1) & (NST - 1);
            uint32_t sa = bsS + st * KCH + tid * 16;
            const unsigned char* ga = gB + (size_t)(t + NST - 1) * KCH + tid * 16;
#pragma unroll
            for (int i = 0; i < 4; i++) cp16(sa + i * 4096, ga + i * 4096);
        }
        cp_commit();

        // B fragments from smem (LDS.128, conflict-free)
        uint32_t bbase = bsS + (uint32_t)(t & (NST - 1)) * KCH + bfrag;
        uint4 bf[8];
#pragma unroll
        for (int nt = 0; nt < 8; nt++) {
            asm volatile("ld.shared.v4.b32 {%0,%1,%2,%3}, [%4];"
                : "=r"(bf[nt].x), "=r"(bf[nt].y), "=r"(bf[nt].z), "=r"(bf[nt].w)
                : "r"(bbase + nt * 512));
        }
        // A fragments
        uint32_t av[2][8];
#pragma unroll
        for (int mt = 0; mt < 2; mt++) {
            uint32_t a0 = aR0 + (uint32_t)(mt * 16 * strideE + t * 16) * 4u;
            uint32_t a8 = a0 + (uint32_t)(8 * strideE) * 4u;
            av[mt][0] = lds32(a0);       av[mt][1] = lds32(a8);
            av[mt][2] = lds32(a0 + 16);  av[mt][3] = lds32(a8 + 16);
            av[mt][4] = lds32(a0 + 32);  av[mt][5] = lds32(a8 + 32);
            av[mt][6] = lds32(a0 + 48);  av[mt][7] = lds32(a8 + 48);
        }
#pragma unroll
        for (int mt = 0; mt < 2; mt++)
#pragma unroll
            for (int nt = 0; nt < 8; nt++)
                mma_tf32(acc[mt][nt], av[mt][0], av[mt][1], av[mt][2], av[mt][3],
                         bf[nt].x, bf[nt].y);
#pragma unroll
        for (int mt = 0; mt < 2; mt++)
#pragma unroll
            for (int nt = 0; nt < 8; nt++)
                mma_tf32(acc[mt][nt], av[mt][4], av[mt][5], av[mt][6], av[mt][7],
                         bf[nt].z, bf[nt].w);
    }
}

// epilogue: relu(acc + bias) -> tf32-rounded fp32 into na smem
__device__ __forceinline__ void epi_write(const float acc[2][8][4],
                                          const float* __restrict__ bias,
                                          uint32_t dst,
                                          int wM, int wN, int lane) {
#pragma unroll
    for (int mt = 0; mt < 2; mt++) {
        int Rb = wM * 32 + mt * 16 + (lane >> 2);
#pragma unroll
        for (int nt = 0; nt < 8; nt++) {
            int C = wN * 64 + nt * 8 + (lane & 3) * 2;
            float bb0 = __ldg(bias + C), bb1 = __ldg(bias + C + 1);
#pragma unroll
            for (int rh = 0; rh < 2; rh++) {
                float v0 = fmaxf(acc[mt][nt][rh * 2 + 0] + bb0, 0.0f);
                float v1 = fmaxf(acc[mt][nt][rh * 2 + 1] + bb1, 0.0f);
                uint32_t off = dst + (uint32_t)((Rb + rh * 8) * SNW + C) * 4u;
                sts64(off, f2tf32(v0), f2tf32(v1));
            }
        }
    }
}

__global__ void __launch_bounds__(THREADS, 1)
decoder_kernel(const float* __restrict__ p,
               const float* __restrict__ c_grid,
               const float* __restrict__ c_xy,
               const float* __restrict__ c_yz,
               const float* __restrict__ c_xz,
               const float* __restrict__ Wp,
               const float* __restrict__ b0g,
               const float* __restrict__ Wout,
               const float* __restrict__ bout,
               float* __restrict__ out) {
    extern __shared__ char smem_raw[];
    SMX& s = *reinterpret_cast<SMX*>(smem_raw);

    const int tid  = threadIdx.x;
    const int wid  = tid >> 5;
    const int lane = tid & 31;
    const int wM   = wid >> 2;      // 0..1
    const int wN   = wid & 3;       // 0..3
    const int q0   = blockIdx.x * MT;

    const uint32_t fa = s2u(s.feat);
    const uint32_t na = s2u(s.na);
    const uint32_t bs = s2u(s.Bst);

    // ---- coordinate prep ----
    if (tid < MT) {
        int q = q0 + tid;
        float x = p[q * 3 + 0], y = p[q * 3 + 1], z = p[q * 3 + 2];
        s.px[tid] = x; s.py[tid] = y; s.pz[tid] = z;
        s.bq[tid] = q / Nn;
        float xn = fminf(fmaxf(x / 1.101f + 0.5f, 0.0f), 1.0f - 1e-5f);
        float yn = fminf(fmaxf(y / 1.101f + 0.5f, 0.0f), 1.0f - 1e-5f);
        float zn = fminf(fmaxf(z / 1.101f + 0.5f, 0.0f), 1.0f - 1e-5f);
        float fgx = xn * (GRES - 1), fgy = yn * (GRES - 1), fgz = zn * (GRES - 1);
        int gx = (int)floorf(fgx), gy = (int)floorf(fgy), gz = (int)floorf(fgz);
        s.gx0[tid] = gx; s.gy0[tid] = gy; s.gz0[tid] = gz;
        s.gwx[tid] = fgx - gx; s.gwy[tid] = fgy - gy; s.gwz[tid] = fgz - gz;
        float fpx = xn * (PRES - 1), fpy = yn * (PRES - 1), fpz = zn * (PRES - 1);
        int px0 = (int)floorf(fpx), py0 = (int)floorf(fpy), pz0 = (int)floorf(fpz);
        s.qx0[tid] = px0; s.qy0[tid] = py0; s.qz0[tid] = pz0;
        s.qwx[tid] = fpx - px0; s.qwy[tid] = fpy - py0; s.qwz[tid] = fpz - pz0;
    }
    __syncthreads();

    // ---- features -> tf32-rounded fp32 feat buffer ----
    for (int task = tid; task < MT * CF; task += THREADS) {
        int pp = task >> 5, ch = task & 31;
        int bc_ch = s.bq[pp] * CF + ch;
        float fv[4];
        {
            const float* g = c_grid + ((size_t)bc_ch << 15);
            int o = (s.gz0[pp] << 10) + (s.gy0[pp] << 5) + s.gx0[pp];
            float wx = s.gwx[pp], wy = s.gwy[pp], wz = s.gwz[pp];
            float v000 = g[o],        v001 = g[o + 1];
            float v010 = g[o + 32],   v011 = g[o + 33];
            float v100 = g[o + 1024], v101 = g[o + 1025];
            float v110 = g[o + 1056], v111 = g[o + 1057];
            float c00 = v000 + (v001 - v000) * wx;
            float c01 = v010 + (v011 - v010) * wx;
            float c10 = v100 + (v101 - v100) * wx;
            float c11 = v110 + (v111 - v110) * wx;
            float cz0 = c00 + (c01 - c00) * wy;
            float cz1 = c10 + (c11 - c10) * wy;
            fv[0] = cz0 + (cz1 - cz0) * wz;
        }
        {
            size_t poff = (size_t)bc_ch << 14;
            int x0 = s.qx0[pp], y0 = s.qy0[pp], z0 = s.qz0[pp];
            float wx = s.qwx[pp], wy = s.qwy[pp], wz = s.qwz[pp];
            fv[1] = bilin(c_xy + poff, x0, y0, wx, wy);
            fv[2] = bilin(c_yz + poff, y0, z0, wy, wz);
            fv[3] = bilin(c_xz + poff, x0, z0, wx, wz);
        }
#pragma unroll
        for (int fk = 0; fk < 4; fk++) {
            int k = fk * 32 + ch;
            sts32(fa + (uint32_t)(pp * SFW + k) * 4u, f2tf32(fv[fk]));
        }
    }

    // ---- net acc init: netA = p @ Wp (biases folded into g_cum) ----
    float accN[2][8][4];
#pragma unroll
    for (int mt = 0; mt < 2; mt++) {
        int Rb = wM * 32 + mt * 16 + (lane >> 2);
#pragma unroll
        for (int nt = 0; nt < 8; nt++) {
            int C = wN * 64 + nt * 8 + (lane & 3) * 2;
            float w00 = __ldg(Wp + C),       w01 = __ldg(Wp + C + 1);
            float w10 = __ldg(Wp + 256 + C), w11 = __ldg(Wp + 256 + C + 1);
            float w20 = __ldg(Wp + 512 + C), w21 = __ldg(Wp + 512 + C + 1);
#pragma unroll
            for (int rh = 0; rh < 2; rh++) {
                int R = Rb + rh * 8;
                float x = s.px[R], y = s.py[R], z = s.pz[R];
                accN[mt][nt][rh * 2 + 0] = x * w00 + y * w10 + z * w20;
                accN[mt][nt][rh * 2 + 1] = x * w01 + y * w11 + z * w21;
            }
        }
    }
    __syncthreads();

    // ---- 5 residual blocks ----
    for (int blk = 0; blk < NBLK; blk++) {
        const unsigned char* bb = g_wblob + (size_t)blk * BLK_STRIDE;
        const float* cum = g_cum + blk * 256;
        const float* b0L = b0g + blk * 256;

        // (a) netA += c @ Wc
        gemm_cp<8>(accN, fa, SFW, bb + L0OFF, bs, wM, wN, lane, tid);

        // (b) tmp = relu(netA + cum) @ W0
        __syncthreads();
        epi_write(accN, cum, na, wM, wN, lane);
        __syncthreads();
        float accT[2][8][4];
#pragma unroll
        for (int mt = 0; mt < 2; mt++)
#pragma unroll
            for (int nt = 0; nt < 8; nt++)
#pragma unroll
                for (int r4 = 0; r4 < 4; r4++) accT[mt][nt][r4] = 0.0f;
        gemm_cp<16>(accT, na, SNW, bb + L1OFF, bs, wM, wN, lane, tid);

        // (c) netA += relu(tmp + b0) @ W1
        __syncthreads();
        epi_write(accT, b0L, na, wM, wN, lane);
        __syncthreads();
        gemm_cp<16>(accN, na, SNW, bb + L2OFF, bs, wM, wN, lane, tid);
    }

    // ---- output: out = relu(netA + cumF) @ Wout + bout ----
    {
        const float* cumF = g_cum + NBLK * 256;
        float part[2][2] = {{0.f, 0.f}, {0.f, 0.f}};
#pragma unroll
        for (int mt = 0; mt < 2; mt++)
#pragma unroll
            for (int nt = 0; nt < 8; nt++) {
                int C = wN * 64 + nt * 8 + (lane & 3) * 2;
                float c0 = __ldg(cumF + C), c1 = __ldg(cumF + C + 1);
                float w0 = __ldg(Wout + C), w1 = __ldg(Wout + C + 1);
#pragma unroll
                for (int rh = 0; rh < 2; rh++) {
                    part[mt][rh] += fmaxf(accN[mt][nt][rh * 2 + 0] + c0, 0.0f) * w0
                                  + fmaxf(accN[mt][nt][rh * 2 + 1] + c1, 0.0f) * w1;
                }
            }
#pragma unroll
        for (int mt = 0; mt < 2; mt++)
#pragma unroll
            for (int rh = 0; rh < 2; rh++) {
                float v = part[mt][rh];
                v += __shfl_xor_sync(0xFFFFFFFFu, v, 1);
                v += __shfl_xor_sync(0xFFFFFFFFu, v, 2);
                if ((lane & 3) == 0) {
                    int R = wM * 32 + mt * 16 + (lane >> 2) + rh * 8;
                    s.outp[R][wN] = v;
                }
            }
        __syncthreads();
        if (tid < MT) {
            float v = s.outp[tid][0] + s.outp[tid][1] + s.outp[tid][2] + s.outp[tid][3]
                    + __ldg(bout);
            out[q0 + tid] = v;
        }
    }
}

extern "C" void kernel_launch(void* const* d_in, const int* in_sizes, int n_in,
                              void* d_out, int out_size) {
    const float* p      = (const float*)d_in[0];
    const float* c_grid = (const float*)d_in[1];
    const float* c_xy   = (const float*)d_in[2];
    const float* c_yz   = (const float*)d_in[3];
    const float* c_xz   = (const float*)d_in[4];
    const float* Wp     = (const float*)d_in[5];
    const float* bp     = (const float*)d_in[6];
    const float* Wc     = (const float*)d_in[7];
    const float* bc     = (const float*)d_in[8];
    const float* W0     = (const float*)d_in[9];
    const float* b0     = (const float*)d_in[10];
    const float* W1     = (const float*)d_in[11];
    const float* b1     = (const float*)d_in[12];
    const float* Wout   = (const float*)d_in[13];
    const float* bout   = (const float*)d_in[14];
    float* out = (float*)d_out;

    int smem = (int)sizeof(SMX);
    cudaFuncSetAttribute(decoder_kernel,
                         cudaFuncAttributeMaxDynamicSharedMemorySize, smem);

    prep_kernel<<<256, 256>>>(Wc, W0, W1, bp, bc, b1);
    decoder_kernel<<<NBLOCKS, THREADS, smem>>>(
        p, c_grid, c_xy, c_yz, c_xz, Wp, b0, Wout, bout, out);
}

// round 17
// speedup vs baseline: 1.7437x; 1.7437x over previous
#include <cuda_runtime.h>
#include <cuda_fp16.h>
#include <stdint.h>
#include <math.h>

#define TOTALP  200000
#define Nn      50000
#define CF      32
#define GRES    32
#define PRES    128
#define HID     256
#define NBLK    5

#define MT      64                   // points per CTA
#define THREADS 256                  // 8 warps: 2 warpM x 4 warpN (warp tile 32x64)
#define NBLOCKS (TOTALP / MT)        // 3125 exact

#define SF      136                  // feature smem row stride (fp16 elems, 128+8)
#define SN      264                  // net smem row stride (fp16 elems, 256+8)

// fp16 weight blob per-block layout (bytes): ktile-contiguous fragment-packed
// ktile = 32 jtiles x 32 lanes x 8 B = 8192 B
#define L0OFF 0                      // Wc  (8 ktiles  = 65536 B)
#define L1OFF 65536                  // W0  (16 ktiles = 131072 B)
#define L2OFF 196608                 // W1  (16 ktiles = 131072 B)
#define BLK_STRIDE 327680

__device__ __align__(16) unsigned char g_wblob[(size_t)NBLK * BLK_STRIDE];
__device__ float g_cum[(NBLK + 1) * HID];

// ---------------- low-level helpers ----------------
__device__ __forceinline__ uint32_t s2u(const void* p) {
    uint32_t a;
    asm("{ .reg .u64 t; cvta.to.shared.u64 t, %1; cvt.u32.u64 %0, t; }" : "=r"(a) : "l"(p));
    return a;
}
__device__ __forceinline__ void sts32(uint32_t a, uint32_t v) {
    asm volatile("st.shared.b32 [%0], %1;" :: "r"(a), "r"(v) : "memory");
}
__device__ __forceinline__ void sts16(uint32_t a, unsigned short v) {
    asm volatile("st.shared.u16 [%0], %1;" :: "r"(a), "h"(v) : "memory");
}
__device__ __forceinline__ void ldm_x4(uint32_t* r, uint32_t addr) {
    asm volatile("ldmatrix.sync.aligned.m8n8.x4.shared.b16 {%0,%1,%2,%3}, [%4];"
                 : "=r"(r[0]), "=r"(r[1]), "=r"(r[2]), "=r"(r[3]) : "r"(addr));
}
// fp16 m16n8k16, fp32 accumulate
__device__ __forceinline__ void mma_fp16(float* d, const uint32_t* a, const uint32_t* b) {
    asm volatile(
        "mma.sync.aligned.m16n8k16.row.col.f32.f16.f16.f32 "
        "{%0,%1,%2,%3}, {%4,%5,%6,%7}, {%8,%9}, {%0,%1,%2,%3};"
        : "+f"(d[0]), "+f"(d[1]), "+f"(d[2]), "+f"(d[3])
        : "r"(a[0]), "r"(a[1]), "r"(a[2]), "r"(a[3]), "r"(b[0]), "r"(b[1]));
}
__device__ __forceinline__ uint32_t pack_h2(float v0, float v1) {
    __half h0 = __float2half_rn(v0), h1 = __float2half_rn(v1);
    return (uint32_t)__half_as_ushort(h0) | ((uint32_t)__half_as_ushort(h1) << 16);
}

// ---------------- prep kernel: fp16-convert + fragment-pack weights ----------------
// Consumer: lane l of (ktile t, jtile j) loads uint2 at ((t*32+j)*32+l)*8:
//   b0 = {W[k0+(l&3)*2][n], W[k0+(l&3)*2+1][n]}, b1 = same + k8, n = j*8 + (l>>2)
__global__ void prep_kernel(const float* __restrict__ Wc, const float* __restrict__ W0,
                            const float* __restrict__ W1, const float* __restrict__ bp,
                            const float* __restrict__ bc, const float* __restrict__ b1) {
    const int total = NBLK * 640 * 256;
    for (int i = blockIdx.x * blockDim.x + threadIdx.x; i < total; i += gridDim.x * blockDim.x) {
        int blk = i / (640 * 256);
        int r   = i % (640 * 256);
        int k   = r / 256;
        int n   = r % 256;
        float w; size_t base; int kl;
        if (k < 128)      { kl = k;       w = Wc[((size_t)blk * 128 + kl) * 256 + n]; base = (size_t)blk * BLK_STRIDE + L0OFF; }
        else if (k < 384) { kl = k - 128; w = W0[((size_t)blk * 256 + kl) * 256 + n]; base = (size_t)blk * BLK_STRIDE + L1OFF; }
        else              { kl = k - 384; w = W1[((size_t)blk * 256 + kl) * 256 + n]; base = (size_t)blk * BLK_STRIDE + L2OFF; }
        int t = kl >> 4, kr = kl & 15;
        int j = n >> 3;
        int lane = ((n & 7) << 2) | ((kr & 7) >> 1);
        int reg = kr >> 3;
        size_t off = base + (size_t)((t * 32 + j) * 32 + lane) * 8 + reg * 4 + (kr & 1) * 2;
        __half h = __float2half_rn(w);
        *(unsigned short*)(g_wblob + off) = __half_as_ushort(h);
    }
    if (blockIdx.x == 0 && threadIdx.x < 256) {
        int c = threadIdx.x;
        float pre = bp[c];
        for (int i = 0; i < NBLK; i++) {
            g_cum[i * 256 + c] = pre + bc[i * 256 + c];
            pre += bc[i * 256 + c] + b1[i * 256 + c];
        }
        g_cum[NBLK * 256 + c] = pre;
    }
}

// ---------------- shared memory ----------------
struct SMX {
    unsigned char feat[MT * SF * 2];   // 17408 B, fp16 activations (K=128)
    unsigned char na[MT * SN * 2];     // 33792 B, fp16 activations (K=256)
    float px[MT], py[MT], pz[MT];
    int   bq[MT];
    int   gx0[MT], gy0[MT], gz0[MT];
    float gwx[MT], gwy[MT], gwz[MT];
    int   qx0[MT], qy0[MT], qz0[MT];
    float qwx[MT], qwy[MT], qwz[MT];
    float outp[MT][4];
};

__device__ __forceinline__ float bilin(const float* __restrict__ base,
                                       int ix, int iy, float wu, float wv) {
    int o = (iy << 7) + ix;
    float a = base[o], b = base[o + 1];
    float c = base[o + 128], d = base[o + 129];
    float t0 = a + (b - a) * wu;
    float t1 = c + (d - c) * wu;
    return t0 + (t1 - t0) * wv;
}

// single-pass fp16 GEMM: acc += A @ W ; warp tile 32 x 64.
// B register-prefetched one ktile ahead (R14 pattern).
template <int KT>
__device__ __forceinline__ void gemm_fp16(float acc[2][8][4],
                                          uint32_t aS, int strideE,
                                          const uint2* __restrict__ gB,
                                          int wM, int wN, int lane) {
    const int rowB = strideE * 2;
    const int grp  = lane >> 3;
    const int arow = (grp & 1) * 8 + (lane & 7);
    const int acolB = (grp >> 1) * 16;
    const uint32_t abase = aS + (uint32_t)((wM * 32 + arow) * rowB) + acolB;
    const uint2* __restrict__ pB = gB + wN * 8 * 32 + lane;

    uint2 bb[2][8];
#pragma unroll
    for (int nt = 0; nt < 8; nt++) bb[0][nt] = __ldg(pB + nt * 32);

#pragma unroll
    for (int t = 0; t < KT; t++) {
        const int cur = t & 1;
        if (t + 1 < KT) {
#pragma unroll
            for (int nt = 0; nt < 8; nt++)
                bb[cur ^ 1][nt] = __ldg(pB + (t + 1) * 1024 + nt * 32);
        }
        uint32_t a[2][4];
#pragma unroll
        for (int mt = 0; mt < 2; mt++) {
            uint32_t off = (uint32_t)(mt * 16 * rowB + t * 32);   // t*16 elems * 2B
            ldm_x4(a[mt], abase + off);
        }
#pragma unroll
        for (int mt = 0; mt < 2; mt++)
#pragma unroll
            for (int nt = 0; nt < 8; nt++)
                mma_fp16(acc[mt][nt], a[mt], (const uint32_t*)&bb[cur][nt]);
    }
}

// epilogue: relu(acc + bias) -> fp16 into na smem (padded row-major)
__device__ __forceinline__ void epi_write(const float acc[2][8][4],
                                          const float* __restrict__ bias,
                                          uint32_t dst,
                                          int wM, int wN, int lane) {
    const int rowB = SN * 2;
#pragma unroll
    for (int mt = 0; mt < 2; mt++) {
        int Rb = wM * 32 + mt * 16 + (lane >> 2);
#pragma unroll
        for (int nt = 0; nt < 8; nt++) {
            int C = wN * 64 + nt * 8 + (lane & 3) * 2;
            float bb0 = __ldg(bias + C), bb1 = __ldg(bias + C + 1);
#pragma unroll
            for (int rh = 0; rh < 2; rh++) {
                float v0 = fmaxf(acc[mt][nt][rh * 2 + 0] + bb0, 0.0f);
                float v1 = fmaxf(acc[mt][nt][rh * 2 + 1] + bb1, 0.0f);
                uint32_t off = dst + (uint32_t)((Rb + rh * 8) * rowB + C * 2);
                sts32(off, pack_h2(v0, v1));
            }
        }
    }
}

__global__ void __launch_bounds__(THREADS, 1)
decoder_kernel(const float* __restrict__ p,
               const float* __restrict__ c_grid,
               const float* __restrict__ c_xy,
               const float* __restrict__ c_yz,
               const float* __restrict__ c_xz,
               const float* __restrict__ Wp,
               const float* __restrict__ b0g,
               const float* __restrict__ Wout,
               const float* __restrict__ bout,
               float* __restrict__ out) {
    extern __shared__ char smem_raw[];
    SMX& s = *reinterpret_cast<SMX*>(smem_raw);

    const int tid  = threadIdx.x;
    const int wid  = tid >> 5;
    const int lane = tid & 31;
    const int wM   = wid >> 2;      // 0..1
    const int wN   = wid & 3;       // 0..3
    const int q0   = blockIdx.x * MT;

    const uint32_t fa = s2u(s.feat);
    const uint32_t na = s2u(s.na);

    // ---- coordinate prep ----
    if (tid < MT) {
        int q = q0 + tid;
        float x = p[q * 3 + 0], y = p[q * 3 + 1], z = p[q * 3 + 2];
        s.px[tid] = x; s.py[tid] = y; s.pz[tid] = z;
        s.bq[tid] = q / Nn;
        float xn = fminf(fmaxf(x / 1.101f + 0.5f, 0.0f), 1.0f - 1e-5f);
        float yn = fminf(fmaxf(y / 1.101f + 0.5f, 0.0f), 1.0f - 1e-5f);
        float zn = fminf(fmaxf(z / 1.101f + 0.5f, 0.0f), 1.0f - 1e-5f);
        float fgx = xn * (GRES - 1), fgy = yn * (GRES - 1), fgz = zn * (GRES - 1);
        int gx = (int)floorf(fgx), gy = (int)floorf(fgy), gz = (int)floorf(fgz);
        s.gx0[tid] = gx; s.gy0[tid] = gy; s.gz0[tid] = gz;
        s.gwx[tid] = fgx - gx; s.gwy[tid] = fgy - gy; s.gwz[tid] = fgz - gz;
        float fpx = xn * (PRES - 1), fpy = yn * (PRES - 1), fpz = zn * (PRES - 1);
        int px0 = (int)floorf(fpx), py0 = (int)floorf(fpy), pz0 = (int)floorf(fpz);
        s.qx0[tid] = px0; s.qy0[tid] = py0; s.qz0[tid] = pz0;
        s.qwx[tid] = fpx - px0; s.qwy[tid] = fpy - py0; s.qwz[tid] = fpz - pz0;
    }
    __syncthreads();

    // ---- features -> fp16 feat buffer (padded row-major) ----
    for (int task = tid; task < MT * CF; task += THREADS) {
        int pp = task >> 5, ch = task & 31;
        int bc_ch = s.bq[pp] * CF + ch;
        float fv[4];
        {
            const float* g = c_grid + ((size_t)bc_ch << 15);
            int o = (s.gz0[pp] << 10) + (s.gy0[pp] << 5) + s.gx0[pp];
            float wx = s.gwx[pp], wy = s.gwy[pp], wz = s.gwz[pp];
            float v000 = g[o],        v001 = g[o + 1];
            float v010 = g[o + 32],   v011 = g[o + 33];
            float v100 = g[o + 1024], v101 = g[o + 1025];
            float v110 = g[o + 1056], v111 = g[o + 1057];
            float c00 = v000 + (v001 - v000) * wx;
            float c01 = v010 + (v011 - v010) * wx;
            float c10 = v100 + (v101 - v100) * wx;
            float c11 = v110 + (v111 - v110) * wx;
            float cz0 = c00 + (c01 - c00) * wy;
            float cz1 = c10 + (c11 - c10) * wy;
            fv[0] = cz0 + (cz1 - cz0) * wz;
        }
        {
            size_t poff = (size_t)bc_ch << 14;
            int x0 = s.qx0[pp], y0 = s.qy0[pp], z0 = s.qz0[pp];
            float wx = s.qwx[pp], wy = s.qwy[pp], wz = s.qwz[pp];
            fv[1] = bilin(c_xy + poff, x0, y0, wx, wy);
            fv[2] = bilin(c_yz + poff, y0, z0, wy, wz);
            fv[3] = bilin(c_xz + poff, x0, z0, wx, wz);
        }
#pragma unroll
        for (int fk = 0; fk < 4; fk++) {
            int k = fk * 32 + ch;
            __half h = __float2half_rn(fv[fk]);
            sts16(fa + (uint32_t)(pp * SF + k) * 2u, __half_as_ushort(h));
        }
    }

    // ---- net acc init: netA = p @ Wp (biases folded into g_cum) ----
    float accN[2][8][4];
#pragma unroll
    for (int mt = 0; mt < 2; mt++) {
        int Rb = wM * 32 + mt * 16 + (lane >> 2);
#pragma unroll
        for (int nt = 0; nt < 8; nt++) {
            int C = wN * 64 + nt * 8 + (lane & 3) * 2;
            float w00 = __ldg(Wp + C),       w01 = __ldg(Wp + C + 1);
            float w10 = __ldg(Wp + 256 + C), w11 = __ldg(Wp + 256 + C + 1);
            float w20 = __ldg(Wp + 512 + C), w21 = __ldg(Wp + 512 + C + 1);
#pragma unroll
            for (int rh = 0; rh < 2; rh++) {
                int R = Rb + rh * 8;
                float x = s.px[R], y = s.py[R], z = s.pz[R];
                accN[mt][nt][rh * 2 + 0] = x * w00 + y * w10 + z * w20;
                accN[mt][nt][rh * 2 + 1] = x * w01 + y * w11 + z * w21;
            }
        }
    }
    __syncthreads();

    // ---- 5 residual blocks ----
    for (int blk = 0; blk < NBLK; blk++) {
        const unsigned char* bb = g_wblob + (size_t)blk * BLK_STRIDE;
        const float* cum = g_cum + blk * 256;
        const float* b0L = b0g + blk * 256;

        // (a) netA += c @ Wc
        gemm_fp16<8>(accN, fa, SF, (const uint2*)(bb + L0OFF), wM, wN, lane);

        // (b) tmp = relu(netA + cum) @ W0
        __syncthreads();
        epi_write(accN, cum, na, wM, wN, lane);
        __syncthreads();
        float accT[2][8][4];
#pragma unroll
        for (int mt = 0; mt < 2; mt++)
#pragma unroll
            for (int nt = 0; nt < 8; nt++)
#pragma unroll
                for (int r4 = 0; r4 < 4; r4++) accT[mt][nt][r4] = 0.0f;
        gemm_fp16<16>(accT, na, SN, (const uint2*)(bb + L1OFF), wM, wN, lane);

        // (c) netA += relu(tmp + b0) @ W1
        __syncthreads();
        epi_write(accT, b0L, na, wM, wN, lane);
        __syncthreads();
        gemm_fp16<16>(accN, na, SN, (const uint2*)(bb + L2OFF), wM, wN, lane);
    }

    // ---- output: out = relu(netA + cumF) @ Wout + bout ----
    {
        const float* cumF = g_cum + NBLK * 256;
        float part[2][2] = {{0.f, 0.f}, {0.f, 0.f}};
#pragma unroll
        for (int mt = 0; mt < 2; mt++)
#pragma unroll
            for (int nt = 0; nt < 8; nt++) {
                int C = wN * 64 + nt * 8 + (lane & 3) * 2;
                float c0 = __ldg(cumF + C), c1 = __ldg(cumF + C + 1);
                float w0 = __ldg(Wout + C), w1 = __ldg(Wout + C + 1);
#pragma unroll
                for (int rh = 0; rh < 2; rh++) {
                    part[mt][rh] += fmaxf(accN[mt][nt][rh * 2 + 0] + c0, 0.0f) * w0
                                  + fmaxf(accN[mt][nt][rh * 2 + 1] + c1, 0.0f) * w1;
                }
            }
#pragma unroll
        for (int mt = 0; mt < 2; mt++)
#pragma unroll
            for (int rh = 0; rh < 2; rh++) {
                float v = part[mt][rh];
                v += __shfl_xor_sync(0xFFFFFFFFu, v, 1);
                v += __shfl_xor_sync(0xFFFFFFFFu, v, 2);
                if ((lane & 3) == 0) {
                    int R = wM * 32 + mt * 16 + (lane >> 2) + rh * 8;
                    s.outp[R][wN] = v;
                }
            }
        __syncthreads();
        if (tid < MT) {
            float v = s.outp[tid][0] + s.outp[tid][1] + s.outp[tid][2] + s.outp[tid][3]
                    + __ldg(bout);
            out[q0 + tid] = v;
        }
    }
}

extern "C" void kernel_launch(void* const* d_in, const int* in_sizes, int n_in,
                              void* d_out, int out_size) {
    const float* p      = (const float*)d_in[0];
    const float* c_grid = (const float*)d_in[1];
    const float* c_xy   = (const float*)d_in[2];
    const float* c_yz   = (const float*)d_in[3];
    const float* c_xz   = (const float*)d_in[4];
    const float* Wp     = (const float*)d_in[5];
    const float* bp     = (const float*)d_in[6];
    const float* Wc     = (const float*)d_in[7];
    const float* bc     = (const float*)d_in[8];
    const float* W0     = (const float*)d_in[9];
    const float* b0     = (const float*)d_in[10];
    const float* W1     = (const float*)d_in[11];
    const float* b1     = (const float*)d_in[12];
    const float* Wout   = (const float*)d_in[13];
    const float* bout   = (const float*)d_in[14];
    float* out = (float*)d_out;

    int smem = (int)sizeof(SMX);
    cudaFuncSetAttribute(decoder_kernel,
                         cudaFuncAttributeMaxDynamicSharedMemorySize, smem);

    prep_kernel<<<256, 256>>>(Wc, W0, W1, bp, bc, b1);
    decoder_kernel<<<NBLOCKS, THREADS, smem>>>(
        p, c_grid, c_xy, c_yz, c_xz, Wp, b0, Wout, bout, out);
}